// round 6
// baseline (speedup 1.0000x reference)
#include <cuda_runtime.h>
#include <cuda_bf16.h>

// Soft local histogram, R=5, bandwidth=0.5.
// Input/output: (4, 8, 3, 256, 256) fp32 -> 96 images of 256x256.
// out[y,x] = sum_{di,dj in [-2,2]} max(0, 1 - 2*|x[y+di,x+dj] - x[y,x]|)
// for y,x in [2, 254); zero on the 2-pixel border.
//
// Tap math: three FFMA-imm (rt=1) per tap, zero alu-pipe ops:
//   d   = fmaf(a, 2.0f, -2c)                    // FFMA-imm
//   w   = __saturatef(fmaf(|d|, -1.0f, 1.0f))   // FFMA.SAT (sat == relu here)
//   acc = fmaf(w, 2.0f, acc)                    // FFMA-imm
// PY=16 column blocking amortizes LDS/addressing/epilogue overhead to ~16%
// of issue slots. 84-reg budget (launch_bounds 256,3) to avoid spills.

#define IMG_H 256
#define IMG_W 256
#define TX 32
#define TYB 8
#define PY 16
#define BH (TYB * PY)          // 128 output rows per block
#define TILE_H (BH + 4)        // 132
#define TILE_W 56              // padded row width in floats
#define NF4 12                 // float4s loaded per row (48 floats)
#define NLOAD (TILE_H * NF4)   // 1584

__global__ __launch_bounds__(TX * TYB, 3) void soft_hist_kernel(
    const float* __restrict__ in, float* __restrict__ out)
{
    __shared__ float tile[TILE_H][TILE_W];

    const int img = blockIdx.z;
    const float* im = in + (size_t)img * IMG_H * IMG_W;
    float* om = out + (size_t)img * IMG_H * IMG_W;

    const int x0 = blockIdx.x * TX;
    const int y0 = blockIdx.y * BH;
    const int tx = threadIdx.x;
    const int ty = threadIdx.y;
    const int tid = ty * TX + tx;

    // Per-block clamped, 16B-aligned load window: 48 floats from base_x.
    // Covers [x0-2, x0+33]; x-clamp shifts only feed the forced-zero border.
    int base_x = x0 - 8;
    if (base_x < 0) base_x = 0;
    if (base_x > IMG_W - 48) base_x = IMG_W - 48;   // 208

    for (int idx = tid; idx < NLOAD; idx += TX * TYB) {
        int ly = idx / NF4;
        int lf = idx - ly * NF4;
        int gy = min(max(y0 + ly - 2, 0), IMG_H - 1);   // clamped rows feed zeros
        float4 v = *reinterpret_cast<const float4*>(im + gy * IMG_W + base_x + lf * 4);
        *reinterpret_cast<float4*>(&tile[ly][4 + lf * 4]) = v;
    }
    __syncthreads();

    const int xoff = x0 - base_x + 2;
    const int rbase = ty * PY;
    const float one = 1.0f;

    float nc2[PY];   // -2 * center
    float acc[PY];   // 2 * running sum (center tap pre-seeded: w == 1)
    #pragma unroll
    for (int k = 0; k < PY; k++) {
        nc2[k] = -2.0f * tile[rbase + k + 2][tx + 2 + xoff];
        acc[k] = 2.0f;
    }

    // Slide over the PY+4 tap rows; each row's 5 values feed up to 5 outputs.
    #pragma unroll
    for (int ry = 0; ry < PY + 4; ry++) {
        float a[5];
        #pragma unroll
        for (int j = 0; j < 5; j++) a[j] = tile[rbase + ry][tx + j + xoff];

        #pragma unroll
        for (int k = 0; k < PY; k++) {
            if (ry >= k && ry <= k + 4) {
                #pragma unroll
                for (int j = 0; j < 5; j++) {
                    if (ry == k + 2 && j == 2) continue;   // center: skipped
                    float d = fmaf(a[j], 2.0f, nc2[k]);                  // FFMA-imm
                    float w = __saturatef(fmaf(fabsf(d), -1.0f, one));   // FFMA.SAT
                    acc[k] = fmaf(w, 2.0f, acc[k]);                      // FFMA-imm
                }
            }
        }
    }

    const int gx = x0 + tx;
    const bool xin = (gx >= 2) && (gx < IMG_W - 2);
    #pragma unroll
    for (int k = 0; k < PY; k++) {
        int gy = y0 + rbase + k;
        bool yin = (gy >= 2) && (gy < IMG_H - 2);
        om[gy * IMG_W + gx] = (xin && yin) ? 0.5f * acc[k] : 0.0f;
    }
}

extern "C" void kernel_launch(void* const* d_in, const int* in_sizes, int n_in,
                              void* d_out, int out_size) {
    const float* in = (const float*)d_in[0];
    float* out = (float*)d_out;
    dim3 block(TX, TYB, 1);
    dim3 grid(IMG_W / TX, IMG_H / BH, 96);   // 8 x 2 x 96 = 1536 blocks
    soft_hist_kernel<<<grid, block>>>(in, out);
}

// round 7
// speedup vs baseline: 1.0917x; 1.0917x over previous
#include <cuda_runtime.h>
#include <cuda_bf16.h>

// Soft local histogram, R=5, bandwidth=0.5.
// Input/output: (4, 8, 3, 256, 256) fp32 -> 96 images of 256x256.
// out[y,x] = sum_{di,dj in [-2,2]} max(0, 1 - 2*|x[y+di,x+dj] - x[y,x]|)
// for y,x in [2, 254); zero on the 2-pixel border.
//
// Tap math: three FFMA-imm (rt=1) per tap, zero alu-pipe ops.
// PX=4 x-vectorization: each thread owns 4 adjacent pixels, so its 12-float
// per-row tap window is 16B-aligned -> 3x LDS.128 per row (vs 20 scalar LDS),
// and the 4 outputs store as one STG.128. PY=2 keeps regs ~40 so occupancy
// stays >= 60% (R6 showed occ < 40% kills issue rate).

#define IMG_H 256
#define IMG_W 256
#define TX 8            // threads in x; each covers PX=4 pixels -> 32 wide
#define TYB 32
#define PX 4
#define PY 2
#define BW 32           // block tile width in pixels
#define BH (TYB * PY)   // 64 output rows per block
#define TILE_H (BH + 4) // 68
#define TILE_W 56       // cols: [0..3] pad, [4..51] loaded, [52..55] pad
#define NF4 12          // float4s loaded per row (48 floats, s in [4,52))
#define NLOAD (TILE_H * NF4)   // 816

__global__ __launch_bounds__(TX * TYB, 5) void soft_hist_kernel(
    const float* __restrict__ in, float* __restrict__ out)
{
    __shared__ float tile[TILE_H][TILE_W];

    const int img = blockIdx.z;
    const float* im = in + (size_t)img * IMG_H * IMG_W;
    float* om = out + (size_t)img * IMG_H * IMG_W;

    const int x0 = blockIdx.x * BW;
    const int y0 = blockIdx.y * BH;
    const int tx = threadIdx.x;
    const int ty = threadIdx.y;
    const int tid = ty * TX + tx;

    // 48-float aligned load window starting at base_x; smem col s = g - base_x + 4.
    // Edge clamps shift the window; pad/garbage cols only ever feed taps whose
    // outputs are in the forced-zero border (verified by index enumeration).
    int base_x = x0 - 8;
    if (base_x < 0) base_x = 0;
    if (base_x > IMG_W - 48) base_x = IMG_W - 48;   // 208

    for (int idx = tid; idx < NLOAD; idx += TX * TYB) {
        int ly = idx / NF4;
        int lf = idx - ly * NF4;
        int gy = min(max(y0 + ly - 2, 0), IMG_H - 1);   // clamped rows feed zeros
        float4 v = *reinterpret_cast<const float4*>(im + gy * IMG_W + base_x + lf * 4);
        *reinterpret_cast<float4*>(&tile[ly][4 + lf * 4]) = v;
    }
    __syncthreads();

    // Thread outputs: cols x0 + 4*tx + p (p=0..3), rows y0 + ty*PY + k (k=0..1).
    // Tap window per row: 12 floats, smem cols [scol0-4, scol0+8), 16B aligned.
    const int scol0 = (x0 + PX * tx) - base_x + 4;   // smem col of output p=0
    const int rbase = ty * PY;
    const float one = 1.0f;

    // Centers: rows rbase+2..rbase+3, cols scol0..scol0+3 -> one LDS.128 each.
    float nc2[PY * PX];
    float acc[PY * PX];
    #pragma unroll
    for (int k = 0; k < PY; k++) {
        float4 c = *reinterpret_cast<const float4*>(&tile[rbase + k + 2][scol0]);
        nc2[k * PX + 0] = -2.0f * c.x;
        nc2[k * PX + 1] = -2.0f * c.y;
        nc2[k * PX + 2] = -2.0f * c.z;
        nc2[k * PX + 3] = -2.0f * c.w;
        acc[k * PX + 0] = 2.0f;   // center tap (w==1) pre-seeded, x2 scale
        acc[k * PX + 1] = 2.0f;
        acc[k * PX + 2] = 2.0f;
        acc[k * PX + 3] = 2.0f;
    }

    // Slide over PY+4 tap rows; 3x LDS.128 per row serve all 4 x-outputs.
    #pragma unroll
    for (int ry = 0; ry < PY + 4; ry++) {
        float a[12];
        #pragma unroll
        for (int q = 0; q < 3; q++) {
            float4 v = *reinterpret_cast<const float4*>(&tile[rbase + ry][scol0 - 4 + q * 4]);
            a[q * 4 + 0] = v.x; a[q * 4 + 1] = v.y;
            a[q * 4 + 2] = v.z; a[q * 4 + 3] = v.w;
        }
        // a[i] holds global col (x0 + 4*tx - 4 + i); tap (p, j) -> a[p + 2 + j].
        #pragma unroll
        for (int k = 0; k < PY; k++) {
            if (ry >= k && ry <= k + 4) {
                #pragma unroll
                for (int p = 0; p < PX; p++) {
                    #pragma unroll
                    for (int j = 0; j < 5; j++) {
                        if (ry == k + 2 && j == 2) continue;   // center: skipped
                        float d = fmaf(a[p + 2 + j], 2.0f, nc2[k * PX + p]);   // FFMA-imm
                        float w = __saturatef(fmaf(fabsf(d), -1.0f, one));     // FFMA.SAT
                        acc[k * PX + p] = fmaf(w, 2.0f, acc[k * PX + p]);      // FFMA-imm
                    }
                }
            }
        }
    }

    // Epilogue: border select + 0.5x scale, one STG.128 per output row.
    const int gxb = x0 + PX * tx;
    #pragma unroll
    for (int k = 0; k < PY; k++) {
        int gy = y0 + rbase + k;
        bool yin = (gy >= 2) && (gy < IMG_H - 2);
        float4 v;
        v.x = (yin && gxb + 0 >= 2 && gxb + 0 < IMG_W - 2) ? 0.5f * acc[k * PX + 0] : 0.0f;
        v.y = (yin && gxb + 1 >= 2 && gxb + 1 < IMG_W - 2) ? 0.5f * acc[k * PX + 1] : 0.0f;
        v.z = (yin && gxb + 2 >= 2 && gxb + 2 < IMG_W - 2) ? 0.5f * acc[k * PX + 2] : 0.0f;
        v.w = (yin && gxb + 3 >= 2 && gxb + 3 < IMG_W - 2) ? 0.5f * acc[k * PX + 3] : 0.0f;
        *reinterpret_cast<float4*>(om + gy * IMG_W + gxb) = v;
    }
}

extern "C" void kernel_launch(void* const* d_in, const int* in_sizes, int n_in,
                              void* d_out, int out_size) {
    const float* in = (const float*)d_in[0];
    float* out = (float*)d_out;
    dim3 block(TX, TYB, 1);
    dim3 grid(IMG_W / BW, IMG_H / BH, 96);   // 8 x 4 x 96 = 3072 blocks
    soft_hist_kernel<<<grid, block>>>(in, out);
}

// round 8
// speedup vs baseline: 1.1741x; 1.0755x over previous
#include <cuda_runtime.h>
#include <cuda_bf16.h>

// Soft local histogram, R=5, bandwidth=0.5.
// Input/output: (4, 8, 3, 256, 256) fp32 -> 96 images of 256x256.
// out[y,x] = sum_{di,dj in [-2,2]} max(0, 1 - 2*|x[y+di,x+dj] - x[y,x]|)
// for y,x in [2, 254); zero on the 2-pixel border.
//
// Tap math: three FFMA-imm (rt=1) per tap, zero alu-pipe ops:
//   d   = fmaf(a, 2.0f, -2c)                    // FFMA-imm
//   w   = __saturatef(fmaf(|d|, -1.0f, 1.0f))   // FFMA.SAT (sat == relu here)
//   acc = fmaf(w, 2.0f, acc)                    // FFMA-imm
// PX=4 x-vectorization: 12-float row window -> 3x LDS.128, outputs STG.128.
// This round: 6 CTAs/SM (42-reg target) to lift occupancy 55% -> ~70% and
// cover LDS latency with more resident warps. Math identical to R7.

#define IMG_H 256
#define IMG_W 256
#define TX 8            // threads in x; each covers PX=4 pixels -> 32 wide
#define TYB 32
#define PX 4
#define PY 2
#define BW 32           // block tile width in pixels
#define BH (TYB * PY)   // 64 output rows per block
#define TILE_H (BH + 4) // 68
#define TILE_W 56       // cols: [0..3] pad, [4..51] loaded, [52..55] pad
#define NF4 12          // float4s loaded per row (48 floats, s in [4,52))
#define NLOAD (TILE_H * NF4)   // 816

__global__ __launch_bounds__(TX * TYB, 6) void soft_hist_kernel(
    const float* __restrict__ in, float* __restrict__ out)
{
    __shared__ float tile[TILE_H][TILE_W];

    const int img = blockIdx.z;
    const float* im = in + (size_t)img * IMG_H * IMG_W;
    float* om = out + (size_t)img * IMG_H * IMG_W;

    const int x0 = blockIdx.x * BW;
    const int y0 = blockIdx.y * BH;
    const int tx = threadIdx.x;
    const int ty = threadIdx.y;
    const int tid = ty * TX + tx;

    // 48-float aligned load window starting at base_x; smem col s = g - base_x + 4.
    // Edge clamps shift the window; pad/garbage cols only ever feed taps whose
    // outputs are in the forced-zero border (verified by index enumeration).
    int base_x = x0 - 8;
    if (base_x < 0) base_x = 0;
    if (base_x > IMG_W - 48) base_x = IMG_W - 48;   // 208

    for (int idx = tid; idx < NLOAD; idx += TX * TYB) {
        int ly = idx / NF4;
        int lf = idx - ly * NF4;
        int gy = min(max(y0 + ly - 2, 0), IMG_H - 1);   // clamped rows feed zeros
        float4 v = *reinterpret_cast<const float4*>(im + gy * IMG_W + base_x + lf * 4);
        *reinterpret_cast<float4*>(&tile[ly][4 + lf * 4]) = v;
    }
    __syncthreads();

    // Thread outputs: cols x0 + 4*tx + p (p=0..3), rows y0 + ty*PY + k (k=0..1).
    // Tap window per row: 12 floats, smem cols [scol0-4, scol0+8), 16B aligned.
    const int scol0 = (x0 + PX * tx) - base_x + 4;   // smem col of output p=0
    const int rbase = ty * PY;
    const float one = 1.0f;

    // Centers: rows rbase+2..rbase+3, cols scol0..scol0+3 -> one LDS.128 each.
    float nc2[PY * PX];
    float acc[PY * PX];
    #pragma unroll
    for (int k = 0; k < PY; k++) {
        float4 c = *reinterpret_cast<const float4*>(&tile[rbase + k + 2][scol0]);
        nc2[k * PX + 0] = -2.0f * c.x;
        nc2[k * PX + 1] = -2.0f * c.y;
        nc2[k * PX + 2] = -2.0f * c.z;
        nc2[k * PX + 3] = -2.0f * c.w;
        acc[k * PX + 0] = 2.0f;   // center tap (w==1) pre-seeded, x2 scale
        acc[k * PX + 1] = 2.0f;
        acc[k * PX + 2] = 2.0f;
        acc[k * PX + 3] = 2.0f;
    }

    // Slide over PY+4 tap rows; 3x LDS.128 per row serve all 4 x-outputs.
    #pragma unroll
    for (int ry = 0; ry < PY + 4; ry++) {
        float a[12];
        #pragma unroll
        for (int q = 0; q < 3; q++) {
            float4 v = *reinterpret_cast<const float4*>(&tile[rbase + ry][scol0 - 4 + q * 4]);
            a[q * 4 + 0] = v.x; a[q * 4 + 1] = v.y;
            a[q * 4 + 2] = v.z; a[q * 4 + 3] = v.w;
        }
        // a[i] holds global col (x0 + 4*tx - 4 + i); tap (p, j) -> a[p + 2 + j].
        #pragma unroll
        for (int k = 0; k < PY; k++) {
            if (ry >= k && ry <= k + 4) {
                #pragma unroll
                for (int p = 0; p < PX; p++) {
                    #pragma unroll
                    for (int j = 0; j < 5; j++) {
                        if (ry == k + 2 && j == 2) continue;   // center: skipped
                        float d = fmaf(a[p + 2 + j], 2.0f, nc2[k * PX + p]);   // FFMA-imm
                        float w = __saturatef(fmaf(fabsf(d), -1.0f, one));     // FFMA.SAT
                        acc[k * PX + p] = fmaf(w, 2.0f, acc[k * PX + p]);      // FFMA-imm
                    }
                }
            }
        }
    }

    // Epilogue: border select + 0.5x scale, one STG.128 per output row.
    const int gxb = x0 + PX * tx;
    #pragma unroll
    for (int k = 0; k < PY; k++) {
        int gy = y0 + rbase + k;
        bool yin = (gy >= 2) && (gy < IMG_H - 2);
        float4 v;
        v.x = (yin && gxb + 0 >= 2 && gxb + 0 < IMG_W - 2) ? 0.5f * acc[k * PX + 0] : 0.0f;
        v.y = (yin && gxb + 1 >= 2 && gxb + 1 < IMG_W - 2) ? 0.5f * acc[k * PX + 1] : 0.0f;
        v.z = (yin && gxb + 2 >= 2 && gxb + 2 < IMG_W - 2) ? 0.5f * acc[k * PX + 2] : 0.0f;
        v.w = (yin && gxb + 3 >= 2 && gxb + 3 < IMG_W - 2) ? 0.5f * acc[k * PX + 3] : 0.0f;
        *reinterpret_cast<float4*>(om + gy * IMG_W + gxb) = v;
    }
}

extern "C" void kernel_launch(void* const* d_in, const int* in_sizes, int n_in,
                              void* d_out, int out_size) {
    const float* in = (const float*)d_in[0];
    float* out = (float*)d_out;
    dim3 block(TX, TYB, 1);
    dim3 grid(IMG_W / BW, IMG_H / BH, 96);   // 8 x 4 x 96 = 3072 blocks
    soft_hist_kernel<<<grid, block>>>(in, out);
}